// round 1
// baseline (speedup 1.0000x reference)
#include <cuda_runtime.h>
#include <cuda_bf16.h>
#include <cstdint>

// Problem constants
#define B_ 4
#define S_ 2048
#define E_ 1024
#define H_ 16
#define D_ 64

// Scratch (device globals; no allocation allowed)
__device__ float g_Q[(size_t)B_ * H_ * S_ * D_];
__device__ float g_K[(size_t)B_ * H_ * S_ * D_];
__device__ float g_V[(size_t)B_ * H_ * S_ * D_];
__device__ float g_AO[(size_t)B_ * S_ * E_];

// ---------------------------------------------------------------------------
// GEMM: C[M,N] = A[M,K] * W[N,K]^T   (nn.Linear semantics, both row-major)
// M = B_*S_ = 8192, N = E_ = 1024, K = E_ = 1024
// Tile 128x128x8, 256 threads, 8x8 microtile.
// SPLIT=true: write to [B, H, S, D] layout (for Q/K/V).
// ---------------------------------------------------------------------------
template <bool SPLIT>
__global__ __launch_bounds__(256) void sgemm_kernel(const float* __restrict__ A,
                                                    const float* __restrict__ W,
                                                    float* __restrict__ C) {
    const int K = E_;
    __shared__ float As[8][132];
    __shared__ float Bs[8][132];

    int tid = threadIdx.x;
    int bm = blockIdx.y * 128;
    int bn = blockIdx.x * 128;

    int lr = tid >> 1;          // 0..127 : row within tile for loading
    int lk = (tid & 1) << 2;    // 0 or 4 : k-offset (float4)
    int tx = tid & 15;          // 0..15
    int ty = tid >> 4;          // 0..15

    float acc[8][8];
#pragma unroll
    for (int i = 0; i < 8; i++)
#pragma unroll
        for (int j = 0; j < 8; j++) acc[i][j] = 0.f;

    const float* Aptr = A + (size_t)(bm + lr) * K + lk;
    const float* Wptr = W + (size_t)(bn + lr) * K + lk;

    for (int k0 = 0; k0 < K; k0 += 8) {
        float4 av = *(const float4*)(Aptr + k0);
        float4 wv = *(const float4*)(Wptr + k0);
        __syncthreads();
        As[lk + 0][lr] = av.x; As[lk + 1][lr] = av.y;
        As[lk + 2][lr] = av.z; As[lk + 3][lr] = av.w;
        Bs[lk + 0][lr] = wv.x; Bs[lk + 1][lr] = wv.y;
        Bs[lk + 2][lr] = wv.z; Bs[lk + 3][lr] = wv.w;
        __syncthreads();

#pragma unroll
        for (int kk = 0; kk < 8; kk++) {
            float4 a0 = *(const float4*)&As[kk][ty * 8];
            float4 a1 = *(const float4*)&As[kk][ty * 8 + 4];
            float4 b0 = *(const float4*)&Bs[kk][tx * 8];
            float4 b1 = *(const float4*)&Bs[kk][tx * 8 + 4];
            float a[8] = {a0.x, a0.y, a0.z, a0.w, a1.x, a1.y, a1.z, a1.w};
            float b[8] = {b0.x, b0.y, b0.z, b0.w, b1.x, b1.y, b1.z, b1.w};
#pragma unroll
            for (int i = 0; i < 8; i++)
#pragma unroll
                for (int j = 0; j < 8; j++) acc[i][j] += a[i] * b[j];
        }
    }

#pragma unroll
    for (int i = 0; i < 8; i++) {
        int m = bm + ty * 8 + i;
        if (!SPLIT) {
            float* cp = C + (size_t)m * E_ + bn + tx * 8;
            *(float4*)(cp + 0) = make_float4(acc[i][0], acc[i][1], acc[i][2], acc[i][3]);
            *(float4*)(cp + 4) = make_float4(acc[i][4], acc[i][5], acc[i][6], acc[i][7]);
        } else {
            int b = m >> 11;       // m / S_
            int s = m & 2047;      // m % S_
#pragma unroll
            for (int jj = 0; jj < 8; jj += 4) {
                int n = bn + tx * 8 + jj;
                int h = n >> 6;
                int d = n & 63;
                float* cp = C + ((((size_t)b * H_ + h) * S_ + s) * D_ + d);
                *(float4*)cp = make_float4(acc[i][jj], acc[i][jj + 1],
                                           acc[i][jj + 2], acc[i][jj + 3]);
            }
        }
    }
}

// ---------------------------------------------------------------------------
// Flash attention (fp32, online softmax). BQ = BKV = 64, D = 64.
// grid: (S/64, B*H). 256 threads: thread t -> (row = t/4, cg = t%4).
// Thread owns 16 keys {cg+4i} for scores, 16 dims (4 float4 at d4 = cg+4g) for O.
// Smem strides chosen conflict-free: Qs/Ks/Ps stride 68, Vs stride 64.
// ---------------------------------------------------------------------------
__global__ __launch_bounds__(256) void flash_kernel(const float* __restrict__ Q,
                                                    const float* __restrict__ K,
                                                    const float* __restrict__ V,
                                                    const int* __restrict__ amask,
                                                    float* __restrict__ out) {
    extern __shared__ float sm[];
    float* Qs = sm;                 // 64 x 68
    float* Ks = Qs + 64 * 68;       // 64 x 68
    float* Ps = Ks + 64 * 68;       // 64 x 68
    float* Vs = Ps + 64 * 68;       // 64 x 64
    __shared__ int mk[64];

    int tid = threadIdx.x;
    int qt = blockIdx.x;            // query tile 0..31
    int bh = blockIdx.y;            // 0..63
    int b = bh >> 4;

    const float* Qb = Q + ((size_t)bh * S_ + qt * 64) * D_;

    // Load Q tile (contiguous 4096 floats) into Qs (stride 68)
    for (int e = tid; e < 1024; e += 256) {
        int r = e >> 4, c4 = e & 15;
        float4 v = ((const float4*)Qb)[e];
        *(float4*)&Qs[r * 68 + c4 * 4] = v;
    }

    int row = tid >> 2;
    int cg = tid & 3;
    int gq = qt * 64 + row;

    float mrun = -1e30f, lrun = 0.f;
    float4 o[4];
#pragma unroll
    for (int g = 0; g < 4; g++) o[g] = make_float4(0.f, 0.f, 0.f, 0.f);

    int ntiles = qt + 1;  // causal
    for (int kt = 0; kt < ntiles; kt++) {
        __syncthreads();  // previous iteration done with Ks/Vs/Ps (and Q ready)
        const float* Kb = K + ((size_t)bh * S_ + kt * 64) * D_;
        const float* Vb = V + ((size_t)bh * S_ + kt * 64) * D_;
        for (int e = tid; e < 1024; e += 256) {
            int r = e >> 4, c4 = e & 15;
            float4 kv = ((const float4*)Kb)[e];
            *(float4*)&Ks[r * 68 + c4 * 4] = kv;
            float4 vv = ((const float4*)Vb)[e];
            ((float4*)Vs)[e] = vv;
        }
        if (tid < 64) mk[tid] = amask[b * S_ + kt * 64 + tid];
        __syncthreads();

        // Scores: s[i] = Q[row] . K[cg+4i]
        float s[16];
#pragma unroll
        for (int i = 0; i < 16; i++) s[i] = 0.f;
        for (int d4 = 0; d4 < 16; d4++) {
            float4 q = *(const float4*)&Qs[row * 68 + d4 * 4];
#pragma unroll
            for (int i = 0; i < 16; i++) {
                float4 kk = *(const float4*)&Ks[(cg + 4 * i) * 68 + d4 * 4];
                s[i] += q.x * kk.x + q.y * kk.y + q.z * kk.z + q.w * kk.w;
            }
        }

        // Scale + mask
        float lmax = -1e30f;
#pragma unroll
        for (int i = 0; i < 16; i++) {
            int kc = cg + 4 * i;
            int gk = kt * 64 + kc;
            s[i] *= 0.125f;  // 1/sqrt(64)
            if (gk > gq || mk[kc] == 0) s[i] = -1e30f;
            lmax = fmaxf(lmax, s[i]);
        }
        lmax = fmaxf(lmax, __shfl_xor_sync(0xffffffffu, lmax, 1));
        lmax = fmaxf(lmax, __shfl_xor_sync(0xffffffffu, lmax, 2));

        float mnew = fmaxf(mrun, lmax);
        float alpha = __expf(mrun - mnew);
        float lsum = 0.f;
#pragma unroll
        for (int i = 0; i < 16; i++) {
            float p = __expf(s[i] - mnew);
            Ps[row * 68 + cg + 4 * i] = p;
            lsum += p;
        }
        lsum += __shfl_xor_sync(0xffffffffu, lsum, 1);
        lsum += __shfl_xor_sync(0xffffffffu, lsum, 2);
        lrun = lrun * alpha + lsum;
        mrun = mnew;
#pragma unroll
        for (int g = 0; g < 4; g++) {
            o[g].x *= alpha; o[g].y *= alpha; o[g].z *= alpha; o[g].w *= alpha;
        }
        __syncthreads();  // all Ps written

        // O += P * V  (thread dims: float4 columns c4 = cg + 4g)
        for (int k4 = 0; k4 < 16; k4++) {
            float4 p = *(const float4*)&Ps[row * 68 + k4 * 4];
#pragma unroll
            for (int g = 0; g < 4; g++) {
                int c4 = cg + 4 * g;
                float4 v0 = *(const float4*)&Vs[(k4 * 4 + 0) * 64 + c4 * 4];
                float4 v1 = *(const float4*)&Vs[(k4 * 4 + 1) * 64 + c4 * 4];
                float4 v2 = *(const float4*)&Vs[(k4 * 4 + 2) * 64 + c4 * 4];
                float4 v3 = *(const float4*)&Vs[(k4 * 4 + 3) * 64 + c4 * 4];
                o[g].x += p.x * v0.x + p.y * v1.x + p.z * v2.x + p.w * v3.x;
                o[g].y += p.x * v0.y + p.y * v1.y + p.z * v2.y + p.w * v3.y;
                o[g].z += p.x * v0.z + p.y * v1.z + p.z * v2.z + p.w * v3.z;
                o[g].w += p.x * v0.w + p.y * v1.w + p.z * v2.w + p.w * v3.w;
            }
        }
    }

    // Epilogue: write to [B, S, H*D]
    float inv = 1.f / lrun;
    int h = bh & 15;
    float* ob = out + ((size_t)(b * S_ + gq)) * E_ + h * D_;
#pragma unroll
    for (int g = 0; g < 4; g++) {
        float4 v = make_float4(o[g].x * inv, o[g].y * inv, o[g].z * inv, o[g].w * inv);
        ((float4*)ob)[cg + 4 * g] = v;
    }
}

// ---------------------------------------------------------------------------
// Launch
// ---------------------------------------------------------------------------
extern "C" void kernel_launch(void* const* d_in, const int* in_sizes, int n_in,
                              void* d_out, int out_size) {
    const float* x     = (const float*)d_in[0];
    const int*   amask = (const int*)d_in[1];
    const float* wq    = (const float*)d_in[2];
    const float* wk    = (const float*)d_in[3];
    const float* wv    = (const float*)d_in[4];
    const float* wo    = (const float*)d_in[5];
    float* out = (float*)d_out;

    float *qp, *kp, *vp, *aop;
    cudaGetSymbolAddress((void**)&qp, g_Q);
    cudaGetSymbolAddress((void**)&kp, g_K);
    cudaGetSymbolAddress((void**)&vp, g_V);
    cudaGetSymbolAddress((void**)&aop, g_AO);

    dim3 gg(E_ / 128, (B_ * S_) / 128);  // (8, 64)

    sgemm_kernel<true><<<gg, 256>>>(x, wq, qp);
    sgemm_kernel<true><<<gg, 256>>>(x, wk, kp);
    sgemm_kernel<true><<<gg, 256>>>(x, wv, vp);

    size_t fa_smem = (3 * 64 * 68 + 64 * 64) * sizeof(float);  // 68608 B
    cudaFuncSetAttribute(flash_kernel, cudaFuncAttributeMaxDynamicSharedMemorySize,
                         (int)fa_smem);
    flash_kernel<<<dim3(S_ / 64, B_ * H_), 256, fa_smem>>>(qp, kp, vp, amask, aop);

    sgemm_kernel<false><<<gg, 256>>>(aop, wo, out);
}

// round 2
// speedup vs baseline: 1.4217x; 1.4217x over previous
#include <cuda_runtime.h>
#include <cuda_bf16.h>
#include <cstdint>

// Problem constants
#define B_ 4
#define S_ 2048
#define E_ 1024
#define H_ 16
#define D_ 64

// Scratch (device globals; no allocation allowed)
__device__ float g_Q[(size_t)B_ * H_ * S_ * D_];
__device__ float g_K[(size_t)B_ * H_ * S_ * D_];
__device__ float g_V[(size_t)B_ * H_ * S_ * D_];
__device__ float g_AO[(size_t)B_ * S_ * E_];

// Swizzled smem offset: tile stored [128][16] fp32, col4-group XORed with (row>>1)&3.
// Conflict-free for float4 global->smem stores AND per-lane mma fragment loads.
__device__ __forceinline__ int SWZ(int r, int c) {
    return r * 16 + ((((c) >> 2) ^ ((r >> 1) & 3)) << 2) + (c & 3);
}

__device__ __forceinline__ float to_tf32(float x) {
    uint32_t u;
    asm("cvt.rna.tf32.f32 %0, %1;" : "=r"(u) : "f"(x));
    return __uint_as_float(u);
}

__device__ __forceinline__ float4 cvt4(float4 v) {
    return make_float4(to_tf32(v.x), to_tf32(v.y), to_tf32(v.z), to_tf32(v.w));
}

__device__ __forceinline__ void mma_tf32(float* c, const uint32_t* a, const uint32_t* b) {
    asm volatile(
        "mma.sync.aligned.m16n8k8.row.col.f32.tf32.tf32.f32 "
        "{%0,%1,%2,%3}, {%4,%5,%6,%7}, {%8,%9}, {%0,%1,%2,%3};"
        : "+f"(c[0]), "+f"(c[1]), "+f"(c[2]), "+f"(c[3])
        : "r"(a[0]), "r"(a[1]), "r"(a[2]), "r"(a[3]), "r"(b[0]), "r"(b[1]));
}

// ---------------------------------------------------------------------------
// TF32 tensor-core GEMM: C[M,N] = A[M,K] * W[N,K]^T
// Tile 128x128x16, 256 threads, warp grid 2x4, warp tile 64x32 (4x4 m16n8 tiles).
// blockIdx.z selects (W, C) pair so Q/K/V run as one launch.
// SPLIT=true writes [B,H,S,D].
// ---------------------------------------------------------------------------
template <bool SPLIT>
__global__ __launch_bounds__(256) void gemm_tf32(
    const float* __restrict__ A,
    const float* __restrict__ W0, const float* __restrict__ W1,
    const float* __restrict__ W2,
    float* __restrict__ C0, float* __restrict__ C1, float* __restrict__ C2) {
    const int K = E_;
    __shared__ float As[128 * 16];
    __shared__ float Bs[128 * 16];

    const float* W = W0;
    float* C = C0;
    if (blockIdx.z == 1) { W = W1; C = C1; }
    else if (blockIdx.z == 2) { W = W2; C = C2; }

    int tid = threadIdx.x;
    int bm = blockIdx.y * 128, bn = blockIdx.x * 128;
    int wid = tid >> 5, lane = tid & 31;
    int lr = lane >> 2, lc = lane & 3;
    int mb = (wid & 1) * 64;    // warp row base within tile
    int nb = (wid >> 1) * 32;   // warp col base within tile

    int ldr = tid >> 2;          // 0..63 (load row)
    int ldc = (tid & 3) << 2;    // 0,4,8,12 (load col)

    const float* Ap = A + (size_t)(bm + ldr) * K + ldc;
    const float* Wp = W + (size_t)(bn + ldr) * K + ldc;

    float acc[4][4][4];
#pragma unroll
    for (int mt = 0; mt < 4; mt++)
#pragma unroll
        for (int nt = 0; nt < 4; nt++)
#pragma unroll
            for (int i = 0; i < 4; i++) acc[mt][nt][i] = 0.f;

    const int s0 = (ldr >> 1) & 3;
    const int s1 = ((ldr + 64) >> 1) & 3;
    const int o0 = ldr * 16 + (((ldc >> 2) ^ s0) << 2);
    const int o1 = (ldr + 64) * 16 + (((ldc >> 2) ^ s1) << 2);

    for (int kc = 0; kc < K; kc += 16) {
        float4 av0 = *(const float4*)(Ap + kc);
        float4 av1 = *(const float4*)(Ap + (size_t)64 * K + kc);
        float4 wv0 = *(const float4*)(Wp + kc);
        float4 wv1 = *(const float4*)(Wp + (size_t)64 * K + kc);
        __syncthreads();
        *(float4*)&As[o0] = cvt4(av0);
        *(float4*)&As[o1] = cvt4(av1);
        *(float4*)&Bs[o0] = cvt4(wv0);
        *(float4*)&Bs[o1] = cvt4(wv1);
        __syncthreads();

#pragma unroll
        for (int k0 = 0; k0 < 16; k0 += 8) {
            uint32_t af[4][4], bf[4][2];
#pragma unroll
            for (int mt = 0; mt < 4; mt++) {
                int m = mb + mt * 16 + lr;
                af[mt][0] = __float_as_uint(As[SWZ(m, k0 + lc)]);
                af[mt][1] = __float_as_uint(As[SWZ(m + 8, k0 + lc)]);
                af[mt][2] = __float_as_uint(As[SWZ(m, k0 + 4 + lc)]);
                af[mt][3] = __float_as_uint(As[SWZ(m + 8, k0 + 4 + lc)]);
            }
#pragma unroll
            for (int nt = 0; nt < 4; nt++) {
                int n = nb + nt * 8 + lr;
                bf[nt][0] = __float_as_uint(Bs[SWZ(n, k0 + lc)]);
                bf[nt][1] = __float_as_uint(Bs[SWZ(n, k0 + 4 + lc)]);
            }
#pragma unroll
            for (int mt = 0; mt < 4; mt++)
#pragma unroll
                for (int nt = 0; nt < 4; nt++)
                    mma_tf32(acc[mt][nt], af[mt], bf[nt]);
        }
    }

    // Epilogue: c0,c1 -> (row, col..col+1); c2,c3 -> (row+8, ...)
#pragma unroll
    for (int mt = 0; mt < 4; mt++) {
#pragma unroll
        for (int nt = 0; nt < 4; nt++) {
            int row = bm + mb + mt * 16 + lr;
            int col = bn + nb + nt * 8 + lc * 2;
#pragma unroll
            for (int half = 0; half < 2; half++) {
                int m = row + half * 8;
                float2 v = make_float2(acc[mt][nt][half * 2],
                                       acc[mt][nt][half * 2 + 1]);
                if (!SPLIT) {
                    *(float2*)(C + (size_t)m * E_ + col) = v;
                } else {
                    int b = m >> 11, s = m & 2047;
                    int h = col >> 6, d = col & 63;
                    *(float2*)(C + ((((size_t)b * H_ + h) * S_ + s) * D_ + d)) = v;
                }
            }
        }
    }
}

// ---------------------------------------------------------------------------
// Flash attention (fp32, online softmax). BQ = BKV = 64, D = 64. (unchanged)
// ---------------------------------------------------------------------------
__global__ __launch_bounds__(256) void flash_kernel(const float* __restrict__ Q,
                                                    const float* __restrict__ K,
                                                    const float* __restrict__ V,
                                                    const int* __restrict__ amask,
                                                    float* __restrict__ out) {
    extern __shared__ float sm[];
    float* Qs = sm;                 // 64 x 68
    float* Ks = Qs + 64 * 68;       // 64 x 68
    float* Ps = Ks + 64 * 68;       // 64 x 68
    float* Vs = Ps + 64 * 68;       // 64 x 64
    __shared__ int mk[64];

    int tid = threadIdx.x;
    int qt = blockIdx.x;
    int bh = blockIdx.y;
    int b = bh >> 4;

    const float* Qb = Q + ((size_t)bh * S_ + qt * 64) * D_;

    for (int e = tid; e < 1024; e += 256) {
        int r = e >> 4, c4 = e & 15;
        float4 v = ((const float4*)Qb)[e];
        *(float4*)&Qs[r * 68 + c4 * 4] = v;
    }

    int row = tid >> 2;
    int cg = tid & 3;
    int gq = qt * 64 + row;

    float mrun = -1e30f, lrun = 0.f;
    float4 o[4];
#pragma unroll
    for (int g = 0; g < 4; g++) o[g] = make_float4(0.f, 0.f, 0.f, 0.f);

    int ntiles = qt + 1;  // causal
    for (int kt = 0; kt < ntiles; kt++) {
        __syncthreads();
        const float* Kb = K + ((size_t)bh * S_ + kt * 64) * D_;
        const float* Vb = V + ((size_t)bh * S_ + kt * 64) * D_;
        for (int e = tid; e < 1024; e += 256) {
            int r = e >> 4, c4 = e & 15;
            float4 kv = ((const float4*)Kb)[e];
            *(float4*)&Ks[r * 68 + c4 * 4] = kv;
            float4 vv = ((const float4*)Vb)[e];
            ((float4*)Vs)[e] = vv;
        }
        if (tid < 64) mk[tid] = amask[b * S_ + kt * 64 + tid];
        __syncthreads();

        float s[16];
#pragma unroll
        for (int i = 0; i < 16; i++) s[i] = 0.f;
        for (int d4 = 0; d4 < 16; d4++) {
            float4 q = *(const float4*)&Qs[row * 68 + d4 * 4];
#pragma unroll
            for (int i = 0; i < 16; i++) {
                float4 kk = *(const float4*)&Ks[(cg + 4 * i) * 68 + d4 * 4];
                s[i] += q.x * kk.x + q.y * kk.y + q.z * kk.z + q.w * kk.w;
            }
        }

        float lmax = -1e30f;
#pragma unroll
        for (int i = 0; i < 16; i++) {
            int kc = cg + 4 * i;
            int gk = kt * 64 + kc;
            s[i] *= 0.125f;
            if (gk > gq || mk[kc] == 0) s[i] = -1e30f;
            lmax = fmaxf(lmax, s[i]);
        }
        lmax = fmaxf(lmax, __shfl_xor_sync(0xffffffffu, lmax, 1));
        lmax = fmaxf(lmax, __shfl_xor_sync(0xffffffffu, lmax, 2));

        float mnew = fmaxf(mrun, lmax);
        float alpha = __expf(mrun - mnew);
        float lsum = 0.f;
#pragma unroll
        for (int i = 0; i < 16; i++) {
            float p = __expf(s[i] - mnew);
            Ps[row * 68 + cg + 4 * i] = p;
            lsum += p;
        }
        lsum += __shfl_xor_sync(0xffffffffu, lsum, 1);
        lsum += __shfl_xor_sync(0xffffffffu, lsum, 2);
        lrun = lrun * alpha + lsum;
        mrun = mnew;
#pragma unroll
        for (int g = 0; g < 4; g++) {
            o[g].x *= alpha; o[g].y *= alpha; o[g].z *= alpha; o[g].w *= alpha;
        }
        __syncthreads();

        for (int k4 = 0; k4 < 16; k4++) {
            float4 p = *(const float4*)&Ps[row * 68 + k4 * 4];
#pragma unroll
            for (int g = 0; g < 4; g++) {
                int c4 = cg + 4 * g;
                float4 v0 = *(const float4*)&Vs[(k4 * 4 + 0) * 64 + c4 * 4];
                float4 v1 = *(const float4*)&Vs[(k4 * 4 + 1) * 64 + c4 * 4];
                float4 v2 = *(const float4*)&Vs[(k4 * 4 + 2) * 64 + c4 * 4];
                float4 v3 = *(const float4*)&Vs[(k4 * 4 + 3) * 64 + c4 * 4];
                o[g].x += p.x * v0.x + p.y * v1.x + p.z * v2.x + p.w * v3.x;
                o[g].y += p.x * v0.y + p.y * v1.y + p.z * v2.y + p.w * v3.y;
                o[g].z += p.x * v0.z + p.y * v1.z + p.z * v2.z + p.w * v3.z;
                o[g].w += p.x * v0.w + p.y * v1.w + p.z * v2.w + p.w * v3.w;
            }
        }
    }

    float inv = 1.f / lrun;
    int h = bh & 15;
    float* ob = out + ((size_t)(b * S_ + gq)) * E_ + h * D_;
#pragma unroll
    for (int g = 0; g < 4; g++) {
        float4 v = make_float4(o[g].x * inv, o[g].y * inv, o[g].z * inv, o[g].w * inv);
        ((float4*)ob)[cg + 4 * g] = v;
    }
}

// ---------------------------------------------------------------------------
// Launch
// ---------------------------------------------------------------------------
extern "C" void kernel_launch(void* const* d_in, const int* in_sizes, int n_in,
                              void* d_out, int out_size) {
    const float* x     = (const float*)d_in[0];
    const int*   amask = (const int*)d_in[1];
    const float* wq    = (const float*)d_in[2];
    const float* wk    = (const float*)d_in[3];
    const float* wv    = (const float*)d_in[4];
    const float* wo    = (const float*)d_in[5];
    float* out = (float*)d_out;

    float *qp, *kp, *vp, *aop;
    cudaGetSymbolAddress((void**)&qp, g_Q);
    cudaGetSymbolAddress((void**)&kp, g_K);
    cudaGetSymbolAddress((void**)&vp, g_V);
    cudaGetSymbolAddress((void**)&aop, g_AO);

    // Fused Q/K/V projections (blockIdx.z picks weight/output)
    gemm_tf32<true><<<dim3(E_ / 128, (B_ * S_) / 128, 3), 256>>>(
        x, wq, wk, wv, qp, kp, vp);

    size_t fa_smem = (3 * 64 * 68 + 64 * 64) * sizeof(float);
    cudaFuncSetAttribute(flash_kernel, cudaFuncAttributeMaxDynamicSharedMemorySize,
                         (int)fa_smem);
    flash_kernel<<<dim3(S_ / 64, B_ * H_), 256, fa_smem>>>(qp, kp, vp, amask, aop);

    // Output projection
    gemm_tf32<false><<<dim3(E_ / 128, (B_ * S_) / 128, 1), 256>>>(
        aop, wo, wo, wo, out, out, out);
}

// round 3
// speedup vs baseline: 4.3123x; 3.0332x over previous
#include <cuda_runtime.h>
#include <cuda_bf16.h>
#include <cstdint>

// Problem constants
#define B_ 4
#define S_ 2048
#define E_ 1024
#define H_ 16
#define D_ 64

// Scratch (device globals; no allocation allowed)
__device__ float g_Q[(size_t)B_ * H_ * S_ * D_];
__device__ float g_K[(size_t)B_ * H_ * S_ * D_];
__device__ float g_V[(size_t)B_ * H_ * S_ * D_];
__device__ float g_AO[(size_t)B_ * S_ * E_];

// Swizzled smem offset for GEMM tiles
__device__ __forceinline__ int SWZ(int r, int c) {
    return r * 16 + ((((c) >> 2) ^ ((r >> 1) & 3)) << 2) + (c & 3);
}

__device__ __forceinline__ float to_tf32(float x) {
    uint32_t u;
    asm("cvt.rna.tf32.f32 %0, %1;" : "=r"(u) : "f"(x));
    return __uint_as_float(u);
}

__device__ __forceinline__ float4 cvt4(float4 v) {
    return make_float4(to_tf32(v.x), to_tf32(v.y), to_tf32(v.z), to_tf32(v.w));
}

__device__ __forceinline__ void mma_tf32(float* c, const uint32_t* a, const uint32_t* b) {
    asm volatile(
        "mma.sync.aligned.m16n8k8.row.col.f32.tf32.tf32.f32 "
        "{%0,%1,%2,%3}, {%4,%5,%6,%7}, {%8,%9}, {%0,%1,%2,%3};"
        : "+f"(c[0]), "+f"(c[1]), "+f"(c[2]), "+f"(c[3])
        : "r"(a[0]), "r"(a[1]), "r"(a[2]), "r"(a[3]), "r"(b[0]), "r"(b[1]));
}

// ---------------------------------------------------------------------------
// TF32 tensor-core GEMM: C[M,N] = A[M,K] * W[N,K]^T  (unchanged from R2)
// ---------------------------------------------------------------------------
template <bool SPLIT>
__global__ __launch_bounds__(256) void gemm_tf32(
    const float* __restrict__ A,
    const float* __restrict__ W0, const float* __restrict__ W1,
    const float* __restrict__ W2,
    float* __restrict__ C0, float* __restrict__ C1, float* __restrict__ C2) {
    const int K = E_;
    __shared__ float As[128 * 16];
    __shared__ float Bs[128 * 16];

    const float* W = W0;
    float* C = C0;
    if (blockIdx.z == 1) { W = W1; C = C1; }
    else if (blockIdx.z == 2) { W = W2; C = C2; }

    int tid = threadIdx.x;
    int bm = blockIdx.y * 128, bn = blockIdx.x * 128;
    int wid = tid >> 5, lane = tid & 31;
    int lr = lane >> 2, lc = lane & 3;
    int mb = (wid & 1) * 64;
    int nb = (wid >> 1) * 32;

    int ldr = tid >> 2;
    int ldc = (tid & 3) << 2;

    const float* Ap = A + (size_t)(bm + ldr) * K + ldc;
    const float* Wp = W + (size_t)(bn + ldr) * K + ldc;

    float acc[4][4][4];
#pragma unroll
    for (int mt = 0; mt < 4; mt++)
#pragma unroll
        for (int nt = 0; nt < 4; nt++)
#pragma unroll
            for (int i = 0; i < 4; i++) acc[mt][nt][i] = 0.f;

    const int s0 = (ldr >> 1) & 3;
    const int s1 = ((ldr + 64) >> 1) & 3;
    const int o0 = ldr * 16 + (((ldc >> 2) ^ s0) << 2);
    const int o1 = (ldr + 64) * 16 + (((ldc >> 2) ^ s1) << 2);

    for (int kc = 0; kc < K; kc += 16) {
        float4 av0 = *(const float4*)(Ap + kc);
        float4 av1 = *(const float4*)(Ap + (size_t)64 * K + kc);
        float4 wv0 = *(const float4*)(Wp + kc);
        float4 wv1 = *(const float4*)(Wp + (size_t)64 * K + kc);
        __syncthreads();
        *(float4*)&As[o0] = cvt4(av0);
        *(float4*)&As[o1] = cvt4(av1);
        *(float4*)&Bs[o0] = cvt4(wv0);
        *(float4*)&Bs[o1] = cvt4(wv1);
        __syncthreads();

#pragma unroll
        for (int k0 = 0; k0 < 16; k0 += 8) {
            uint32_t af[4][4], bf[4][2];
#pragma unroll
            for (int mt = 0; mt < 4; mt++) {
                int m = mb + mt * 16 + lr;
                af[mt][0] = __float_as_uint(As[SWZ(m, k0 + lc)]);
                af[mt][1] = __float_as_uint(As[SWZ(m + 8, k0 + lc)]);
                af[mt][2] = __float_as_uint(As[SWZ(m, k0 + 4 + lc)]);
                af[mt][3] = __float_as_uint(As[SWZ(m + 8, k0 + 4 + lc)]);
            }
#pragma unroll
            for (int nt = 0; nt < 4; nt++) {
                int n = nb + nt * 8 + lr;
                bf[nt][0] = __float_as_uint(Bs[SWZ(n, k0 + lc)]);
                bf[nt][1] = __float_as_uint(Bs[SWZ(n, k0 + 4 + lc)]);
            }
#pragma unroll
            for (int mt = 0; mt < 4; mt++)
#pragma unroll
                for (int nt = 0; nt < 4; nt++)
                    mma_tf32(acc[mt][nt], af[mt], bf[nt]);
        }
    }

#pragma unroll
    for (int mt = 0; mt < 4; mt++) {
#pragma unroll
        for (int nt = 0; nt < 4; nt++) {
            int row = bm + mb + mt * 16 + lr;
            int col = bn + nb + nt * 8 + lc * 2;
#pragma unroll
            for (int half = 0; half < 2; half++) {
                int m = row + half * 8;
                float2 v = make_float2(acc[mt][nt][half * 2],
                                       acc[mt][nt][half * 2 + 1]);
                if (!SPLIT) {
                    *(float2*)(C + (size_t)m * E_ + col) = v;
                } else {
                    int b = m >> 11, s = m & 2047;
                    int h = col >> 6, d = col & 63;
                    *(float2*)(C + ((((size_t)b * H_ + h) * S_ + s) * D_ + d)) = v;
                }
            }
        }
    }
}

// ---------------------------------------------------------------------------
// Tensor-core flash attention (tf32 mma, fp32 softmax).
// BQ=128, BKV=64, D=64. 8 warps x 16 q-rows. grid (S/128, B*H).
// Smem: Qs[128][68], Ks[64][68], Vs[64][72] — conflict-free for the exact
// fragment LDS patterns. P never touches smem (intra-quad shuffle relayout).
// ---------------------------------------------------------------------------
__global__ __launch_bounds__(256) void flash_tc(const float* __restrict__ Q,
                                                const float* __restrict__ K,
                                                const float* __restrict__ V,
                                                const int* __restrict__ amask,
                                                float* __restrict__ out) {
    extern __shared__ float sm[];
    float* Qs = sm;                    // 128 x 68
    float* Ks = Qs + 128 * 68;         // 64 x 68
    float* Vs = Ks + 64 * 68;          // 64 x 72
    __shared__ unsigned mkb[2];

    const int tid = threadIdx.x;
    const int qt = blockIdx.x;
    const int bh = blockIdx.y;
    const int b = bh >> 4, h = bh & 15;
    const int qbase = qt * 128;

    const int lane = tid & 31, wid = tid >> 5;
    const int lr = lane >> 2, lc = lane & 3;
    const int wb = wid * 16;           // warp's q-row base within tile

    // Load Q tile (scale by 1/8, round to tf32)
    {
        const float* Qb = Q + ((size_t)bh * S_ + qbase) * D_;
        for (int e = tid; e < 2048; e += 256) {
            int r = e >> 4, c4 = e & 15;
            float4 v = ((const float4*)Qb)[e];
            v.x *= 0.125f; v.y *= 0.125f; v.z *= 0.125f; v.w *= 0.125f;
            *(float4*)&Qs[r * 68 + c4 * 4] = cvt4(v);
        }
    }

    const int grow0 = qbase + wb + lr;   // rows for c0/c1
    const int grow1 = grow0 + 8;         // rows for c2/c3

    float oacc[8][4];
#pragma unroll
    for (int nt = 0; nt < 8; nt++)
#pragma unroll
        for (int j = 0; j < 4; j++) oacc[nt][j] = 0.f;

    float mlo = -1e30f, mhi = -1e30f, llo = 0.f, lhi = 0.f;

    const int ntiles = 2 * qt + 2;
    for (int kt = 0; kt < ntiles; kt++) {
        __syncthreads();  // prev iteration done with Ks/Vs; Qs ready (iter 0)

        // Load K, V tiles (tf32-rounded)
        const float* Kb = K + ((size_t)bh * S_ + kt * 64) * D_;
        const float* Vb = V + ((size_t)bh * S_ + kt * 64) * D_;
        for (int e = tid; e < 1024; e += 256) {
            int r = e >> 4, c4 = e & 15;
            float4 kv = ((const float4*)Kb)[e];
            *(float4*)&Ks[r * 68 + c4 * 4] = cvt4(kv);
            float4 vv = ((const float4*)Vb)[e];
            *(float4*)&Vs[r * 72 + c4 * 4] = cvt4(vv);
        }
        if (tid < 64) {
            int m = amask[b * S_ + kt * 64 + tid];
            unsigned bal = __ballot_sync(0xffffffffu, m != 0);
            if ((tid & 31) == 0) mkb[tid >> 5] = bal;
        }
        __syncthreads();

        // ---- S = Q K^T (per-warp 16x64 via 8 n-tiles) ----
        float sacc[8][4];
#pragma unroll
        for (int nt = 0; nt < 8; nt++)
#pragma unroll
            for (int j = 0; j < 4; j++) sacc[nt][j] = 0.f;

#pragma unroll
        for (int ks = 0; ks < 8; ks++) {
            int k0 = ks * 8;
            uint32_t a[4];
            a[0] = __float_as_uint(Qs[(wb + lr) * 68 + k0 + lc]);
            a[1] = __float_as_uint(Qs[(wb + lr + 8) * 68 + k0 + lc]);
            a[2] = __float_as_uint(Qs[(wb + lr) * 68 + k0 + 4 + lc]);
            a[3] = __float_as_uint(Qs[(wb + lr + 8) * 68 + k0 + 4 + lc]);
#pragma unroll
            for (int nt = 0; nt < 8; nt++) {
                uint32_t bb[2];
                bb[0] = __float_as_uint(Ks[(nt * 8 + lr) * 68 + k0 + lc]);
                bb[1] = __float_as_uint(Ks[(nt * 8 + lr) * 68 + k0 + 4 + lc]);
                mma_tf32(sacc[nt], a, bb);
            }
        }

        // ---- mask ----
        unsigned mb0 = mkb[0], mb1 = mkb[1];
        bool diag = (kt >= 2 * qt);
        bool pad = (mb0 & mb1) != 0xffffffffu;
        if (diag || pad) {
#pragma unroll
            for (int nt = 0; nt < 8; nt++) {
#pragma unroll
                for (int j = 0; j < 4; j++) {
                    int colL = nt * 8 + 2 * lc + (j & 1);
                    int gcol = kt * 64 + colL;
                    int grow = (j < 2) ? grow0 : grow1;
                    unsigned bit = ((colL < 32 ? mb0 : mb1) >> (colL & 31)) & 1u;
                    if (!bit || gcol > grow) sacc[nt][j] = -1e30f;
                }
            }
        }

        // ---- online softmax on fragments ----
        float tlo = -1e30f, thi = -1e30f;
#pragma unroll
        for (int nt = 0; nt < 8; nt++) {
            tlo = fmaxf(tlo, fmaxf(sacc[nt][0], sacc[nt][1]));
            thi = fmaxf(thi, fmaxf(sacc[nt][2], sacc[nt][3]));
        }
        tlo = fmaxf(tlo, __shfl_xor_sync(0xffffffffu, tlo, 1));
        tlo = fmaxf(tlo, __shfl_xor_sync(0xffffffffu, tlo, 2));
        thi = fmaxf(thi, __shfl_xor_sync(0xffffffffu, thi, 1));
        thi = fmaxf(thi, __shfl_xor_sync(0xffffffffu, thi, 2));

        float nmlo = fmaxf(mlo, tlo), nmhi = fmaxf(mhi, thi);
        float alo = __expf(mlo - nmlo), ahi = __expf(mhi - nmhi);
        mlo = nmlo; mhi = nmhi;

        float slo = 0.f, shi = 0.f;
#pragma unroll
        for (int nt = 0; nt < 8; nt++) {
            float p0 = to_tf32(__expf(sacc[nt][0] - nmlo));
            float p1 = to_tf32(__expf(sacc[nt][1] - nmlo));
            float p2 = to_tf32(__expf(sacc[nt][2] - nmhi));
            float p3 = to_tf32(__expf(sacc[nt][3] - nmhi));
            sacc[nt][0] = p0; sacc[nt][1] = p1;
            sacc[nt][2] = p2; sacc[nt][3] = p3;
            slo += p0 + p1; shi += p2 + p3;
        }
        slo += __shfl_xor_sync(0xffffffffu, slo, 1);
        slo += __shfl_xor_sync(0xffffffffu, slo, 2);
        shi += __shfl_xor_sync(0xffffffffu, shi, 1);
        shi += __shfl_xor_sync(0xffffffffu, shi, 2);
        llo = llo * alo + slo;
        lhi = lhi * ahi + shi;

#pragma unroll
        for (int nt = 0; nt < 8; nt++) {
            oacc[nt][0] *= alo; oacc[nt][1] *= alo;
            oacc[nt][2] *= ahi; oacc[nt][3] *= ahi;
        }

        // ---- O += P V ; P fragments via intra-quad shuffles ----
        const int src0 = (lane & 28) | (lc >> 1);
        const int src1 = src0 + 2;
#pragma unroll
        for (int ks = 0; ks < 8; ks++) {
            float p0 = sacc[ks][0], p1 = sacc[ks][1];
            float p2 = sacc[ks][2], p3 = sacc[ks][3];
            float u0 = __shfl_sync(0xffffffffu, p0, src0);
            float u1 = __shfl_sync(0xffffffffu, p1, src0);
            float u2 = __shfl_sync(0xffffffffu, p2, src0);
            float u3 = __shfl_sync(0xffffffffu, p3, src0);
            float v0 = __shfl_sync(0xffffffffu, p0, src1);
            float v1 = __shfl_sync(0xffffffffu, p1, src1);
            float v2 = __shfl_sync(0xffffffffu, p2, src1);
            float v3 = __shfl_sync(0xffffffffu, p3, src1);
            uint32_t a[4];
            a[0] = __float_as_uint((lc & 1) ? u1 : u0);
            a[1] = __float_as_uint((lc & 1) ? u3 : u2);
            a[2] = __float_as_uint((lc & 1) ? v1 : v0);
            a[3] = __float_as_uint((lc & 1) ? v3 : v2);
#pragma unroll
            for (int nt = 0; nt < 8; nt++) {
                uint32_t bb[2];
                bb[0] = __float_as_uint(Vs[(ks * 8 + lc) * 72 + nt * 8 + lr]);
                bb[1] = __float_as_uint(Vs[(ks * 8 + 4 + lc) * 72 + nt * 8 + lr]);
                mma_tf32(oacc[nt], a, bb);
            }
        }
    }

    // Epilogue: out[b, s, h*64 + d]
    float il0 = 1.f / llo, il1 = 1.f / lhi;
#pragma unroll
    for (int nt = 0; nt < 8; nt++) {
        int col = nt * 8 + 2 * lc;
        float* p0 = out + ((size_t)b * S_ + grow0) * E_ + h * D_ + col;
        float* p1 = out + ((size_t)b * S_ + grow1) * E_ + h * D_ + col;
        *(float2*)p0 = make_float2(oacc[nt][0] * il0, oacc[nt][1] * il0);
        *(float2*)p1 = make_float2(oacc[nt][2] * il1, oacc[nt][3] * il1);
    }
}

// ---------------------------------------------------------------------------
// Launch
// ---------------------------------------------------------------------------
extern "C" void kernel_launch(void* const* d_in, const int* in_sizes, int n_in,
                              void* d_out, int out_size) {
    const float* x     = (const float*)d_in[0];
    const int*   amask = (const int*)d_in[1];
    const float* wq    = (const float*)d_in[2];
    const float* wk    = (const float*)d_in[3];
    const float* wv    = (const float*)d_in[4];
    const float* wo    = (const float*)d_in[5];
    float* out = (float*)d_out;

    float *qp, *kp, *vp, *aop;
    cudaGetSymbolAddress((void**)&qp, g_Q);
    cudaGetSymbolAddress((void**)&kp, g_K);
    cudaGetSymbolAddress((void**)&vp, g_V);
    cudaGetSymbolAddress((void**)&aop, g_AO);

    // Fused Q/K/V projections
    gemm_tf32<true><<<dim3(E_ / 128, (B_ * S_) / 128, 3), 256>>>(
        x, wq, wk, wv, qp, kp, vp);

    // Tensor-core flash attention
    size_t fa_smem = (128 * 68 + 64 * 68 + 64 * 72) * sizeof(float);  // 70656 B
    cudaFuncSetAttribute(flash_tc, cudaFuncAttributeMaxDynamicSharedMemorySize,
                         (int)fa_smem);
    flash_tc<<<dim3(S_ / 128, B_ * H_), 256, fa_smem>>>(qp, kp, vp, amask, aop);

    // Output projection
    gemm_tf32<false><<<dim3(E_ / 128, (B_ * S_) / 128, 1), 256>>>(
        aop, wo, wo, wo, out, out, out);
}